// round 4
// baseline (speedup 1.0000x reference)
#include <cuda_runtime.h>
#include <cuda_bf16.h>
#include <cstdint>

// Problem constants (fixed by reference)
#define B_ROWS 4096
#define D_DIM  1024
#define NV     8192
#define NBUK   64      // 48 real buckets (6 concepts x 8), padded to 64

// ---------------- static scratch (no allocations allowed) ----------------
__device__ __nv_bfloat16 g_Ebf[B_ROWS * D_DIM];            // 8 MB
__device__ __nv_bfloat16 g_Wbf[NV * D_DIM];                // 16 MB
__device__ __nv_bfloat16 g_S[NBUK * NV];                   // 1 MB  (row n = concept*8+outcome, over j)
__device__ __nv_bfloat16 g_EXP[(size_t)B_ROWS * NV];       // 64 MB (unnormalized exp of logits)
__device__ float         g_U[B_ROWS * NBUK];               // 1 MB  (bucket sums)

// ---------------- prep kernels ----------------
__global__ void conv_e_kernel(const float* __restrict__ E) {
    int idx = blockIdx.x * blockDim.x + threadIdx.x;       // one float4 per thread
    if (idx < B_ROWS * D_DIM / 4) {
        float4 v = reinterpret_cast<const float4*>(E)[idx];
        __nv_bfloat162* dst = reinterpret_cast<__nv_bfloat162*>(g_Ebf);
        dst[idx * 2 + 0] = __floats2bfloat162_rn(v.x, v.y);
        dst[idx * 2 + 1] = __floats2bfloat162_rn(v.z, v.w);
    }
}

__global__ void conv_w_kernel(const float* __restrict__ W) {
    int idx = blockIdx.x * blockDim.x + threadIdx.x;
    if (idx < NV * D_DIM / 4) {
        float4 v = reinterpret_cast<const float4*>(W)[idx];
        __nv_bfloat162* dst = reinterpret_cast<__nv_bfloat162*>(g_Wbf);
        dst[idx * 2 + 0] = __floats2bfloat162_rn(v.x, v.y);
        dst[idx * 2 + 1] = __floats2bfloat162_rn(v.z, v.w);
    }
}

__global__ void build_s_kernel(const int* __restrict__ valid_states) {
    int i = blockIdx.x * blockDim.x + threadIdx.x;         // over 64*8192
    if (i < NBUK * NV) {
        int n = i >> 13;            // bucket row 0..63
        int j = i & (NV - 1);       // valid-state column
        float val = 0.0f;
        int c = n >> 3;
        if (c < 6) {
            int vs = valid_states[j];
            int digit = (vs >> (3 * (5 - c))) & 7;
            val = (digit == (n & 7)) ? 1.0f : 0.0f;
        }
        g_S[i] = __float2bfloat16(val);
    }
}

__global__ void zero_u_kernel() {
    int idx = blockIdx.x * blockDim.x + threadIdx.x;
    if (idx < B_ROWS * NBUK / 4)
        reinterpret_cast<float4*>(g_U)[idx] = make_float4(0.f, 0.f, 0.f, 0.f);
}

// ---------------- mma helper ----------------
__device__ __forceinline__ void mma_bf16(float4& c, const uint32_t a[4], const uint32_t b[2]) {
    asm volatile(
        "mma.sync.aligned.m16n8k16.row.col.f32.bf16.bf16.f32 "
        "{%0,%1,%2,%3}, {%4,%5,%6,%7}, {%8,%9}, {%0,%1,%2,%3};\n"
        : "+f"(c.x), "+f"(c.y), "+f"(c.z), "+f"(c.w)
        : "r"(a[0]), "r"(a[1]), "r"(a[2]), "r"(a[3]), "r"(b[0]), "r"(b[1]));
}

// ---------------- GEMM1: EXP = exp(Ebf @ Wbf^T + bias) ----------------
// BM=128 BN=128 BK=32, 256 threads (warp grid 2M x 4N, warp tile 64x32)
#define A_STRIDE 40   // bf16 elems per smem row (80B: conflict-free & 8B aligned)

__global__ void __launch_bounds__(256, 2)
gemm_exp_kernel(const float* __restrict__ bias) {
    __shared__ __nv_bfloat16 As[128 * A_STRIDE];
    __shared__ __nv_bfloat16 Bs[128 * A_STRIDE];

    const int tid = threadIdx.x;
    const int lane = tid & 31, wid = tid >> 5;
    const int warp_m = wid & 1;        // 0..1
    const int warp_n = wid >> 1;       // 0..3
    const int block_n = blockIdx.x;    // 0..63
    const int block_m = blockIdx.y;    // 0..31

    float4 acc[4][4];
    #pragma unroll
    for (int mi = 0; mi < 4; mi++)
        #pragma unroll
        for (int ni = 0; ni < 4; ni++)
            acc[mi][ni] = make_float4(0.f, 0.f, 0.f, 0.f);

    for (int k0 = 0; k0 < D_DIM; k0 += 32) {
        // stage A: 128x32 bf16; 512 uint4 total, 2 per thread
        #pragma unroll
        for (int i = 0; i < 2; i++) {
            int u = tid + i * 256;
            int row = u >> 2;
            int col = (u & 3) * 8;
            uint4 v = *reinterpret_cast<const uint4*>(
                &g_Ebf[(block_m * 128 + row) * D_DIM + k0 + col]);
            *reinterpret_cast<uint2*>(&As[row * A_STRIDE + col])     = make_uint2(v.x, v.y);
            *reinterpret_cast<uint2*>(&As[row * A_STRIDE + col + 4]) = make_uint2(v.z, v.w);
            uint4 w = *reinterpret_cast<const uint4*>(
                &g_Wbf[(block_n * 128 + row) * D_DIM + k0 + col]);
            *reinterpret_cast<uint2*>(&Bs[row * A_STRIDE + col])     = make_uint2(w.x, w.y);
            *reinterpret_cast<uint2*>(&Bs[row * A_STRIDE + col + 4]) = make_uint2(w.z, w.w);
        }
        __syncthreads();

        #pragma unroll
        for (int ks = 0; ks < 2; ks++) {
            const int kb = ks * 16 + (lane & 3) * 2;
            uint32_t af[4][4], bf[4][2];
            #pragma unroll
            for (int mi = 0; mi < 4; mi++) {
                int r = warp_m * 64 + mi * 16 + (lane >> 2);
                af[mi][0] = *reinterpret_cast<const uint32_t*>(&As[r * A_STRIDE + kb]);
                af[mi][1] = *reinterpret_cast<const uint32_t*>(&As[(r + 8) * A_STRIDE + kb]);
                af[mi][2] = *reinterpret_cast<const uint32_t*>(&As[r * A_STRIDE + kb + 8]);
                af[mi][3] = *reinterpret_cast<const uint32_t*>(&As[(r + 8) * A_STRIDE + kb + 8]);
            }
            #pragma unroll
            for (int ni = 0; ni < 4; ni++) {
                int n = warp_n * 32 + ni * 8 + (lane >> 2);
                bf[ni][0] = *reinterpret_cast<const uint32_t*>(&Bs[n * A_STRIDE + kb]);
                bf[ni][1] = *reinterpret_cast<const uint32_t*>(&Bs[n * A_STRIDE + kb + 8]);
            }
            #pragma unroll
            for (int mi = 0; mi < 4; mi++)
                #pragma unroll
                for (int ni = 0; ni < 4; ni++)
                    mma_bf16(acc[mi][ni], af[mi], bf[ni]);
        }
        __syncthreads();
    }

    // epilogue: add bias, exp, store bf16
    #pragma unroll
    for (int mi = 0; mi < 4; mi++) {
        int r0 = block_m * 128 + warp_m * 64 + mi * 16 + (lane >> 2);
        #pragma unroll
        for (int ni = 0; ni < 4; ni++) {
            int n0 = block_n * 128 + warp_n * 32 + ni * 8 + (lane & 3) * 2;
            float b0 = bias[n0], b1 = bias[n0 + 1];
            float4 c = acc[mi][ni];
            float e0 = __expf(c.x + b0);
            float e1 = __expf(c.y + b1);
            float e2 = __expf(c.z + b0);
            float e3 = __expf(c.w + b1);
            *reinterpret_cast<__nv_bfloat162*>(&g_EXP[(size_t)r0 * NV + n0]) =
                __floats2bfloat162_rn(e0, e1);
            *reinterpret_cast<__nv_bfloat162*>(&g_EXP[(size_t)(r0 + 8) * NV + n0]) =
                __floats2bfloat162_rn(e2, e3);
        }
    }
}

// ---------------- GEMM2: U += EXP @ S^T (split-K=8, atomic epilogue) ----------------
// BM=128, BN=64, BK=64, 256 threads (warp grid 4M x 2N, warp tile 32x32)
#define B_STRIDE 72   // bf16 elems per smem row (144B: conflict-free & 16B aligned)

__global__ void __launch_bounds__(256, 2)
gemm_bucket_kernel() {
    __shared__ __nv_bfloat16 As[128 * B_STRIDE];
    __shared__ __nv_bfloat16 Bs[64 * B_STRIDE];

    const int tid = threadIdx.x;
    const int lane = tid & 31, wid = tid >> 5;
    const int warp_m = wid >> 1;       // 0..3
    const int warp_n = wid & 1;        // 0..1
    const int ksplit = blockIdx.x;     // 0..7
    const int block_m = blockIdx.y;    // 0..31
    const int kbase = ksplit * (NV / 8);

    float4 acc[2][4];
    #pragma unroll
    for (int mi = 0; mi < 2; mi++)
        #pragma unroll
        for (int ni = 0; ni < 4; ni++)
            acc[mi][ni] = make_float4(0.f, 0.f, 0.f, 0.f);

    for (int k0 = 0; k0 < NV / 8; k0 += 64) {
        // stage A: 128x64 bf16 = 1024 uint4, 4 per thread
        #pragma unroll
        for (int i = 0; i < 4; i++) {
            int u = tid + i * 256;
            int row = u >> 3;
            int col = (u & 7) * 8;
            uint4 v = *reinterpret_cast<const uint4*>(
                &g_EXP[(size_t)(block_m * 128 + row) * NV + kbase + k0 + col]);
            *reinterpret_cast<uint4*>(&As[row * B_STRIDE + col]) = v;
        }
        // stage B (selector): 64x64 bf16 = 512 uint4, 2 per thread
        #pragma unroll
        for (int i = 0; i < 2; i++) {
            int u = tid + i * 256;
            int row = u >> 3;
            int col = (u & 7) * 8;
            uint4 v = *reinterpret_cast<const uint4*>(&g_S[row * NV + kbase + k0 + col]);
            *reinterpret_cast<uint4*>(&Bs[row * B_STRIDE + col]) = v;
        }
        __syncthreads();

        #pragma unroll
        for (int ks = 0; ks < 4; ks++) {
            const int kb = ks * 16 + (lane & 3) * 2;
            uint32_t af[2][4], bf[4][2];
            #pragma unroll
            for (int mi = 0; mi < 2; mi++) {
                int r = warp_m * 32 + mi * 16 + (lane >> 2);
                af[mi][0] = *reinterpret_cast<const uint32_t*>(&As[r * B_STRIDE + kb]);
                af[mi][1] = *reinterpret_cast<const uint32_t*>(&As[(r + 8) * B_STRIDE + kb]);
                af[mi][2] = *reinterpret_cast<const uint32_t*>(&As[r * B_STRIDE + kb + 8]);
                af[mi][3] = *reinterpret_cast<const uint32_t*>(&As[(r + 8) * B_STRIDE + kb + 8]);
            }
            #pragma unroll
            for (int ni = 0; ni < 4; ni++) {
                int n = warp_n * 32 + ni * 8 + (lane >> 2);
                bf[ni][0] = *reinterpret_cast<const uint32_t*>(&Bs[n * B_STRIDE + kb]);
                bf[ni][1] = *reinterpret_cast<const uint32_t*>(&Bs[n * B_STRIDE + kb + 8]);
            }
            #pragma unroll
            for (int mi = 0; mi < 2; mi++)
                #pragma unroll
                for (int ni = 0; ni < 4; ni++)
                    mma_bf16(acc[mi][ni], af[mi], bf[ni]);
        }
        __syncthreads();
    }

    // atomic epilogue into U
    #pragma unroll
    for (int mi = 0; mi < 2; mi++) {
        int r0 = block_m * 128 + warp_m * 32 + mi * 16 + (lane >> 2);
        #pragma unroll
        for (int ni = 0; ni < 4; ni++) {
            int n0 = warp_n * 32 + ni * 8 + (lane & 3) * 2;
            float4 c = acc[mi][ni];
            atomicAdd(&g_U[r0 * NBUK + n0],           c.x);
            atomicAdd(&g_U[r0 * NBUK + n0 + 1],       c.y);
            atomicAdd(&g_U[(r0 + 8) * NBUK + n0],     c.z);
            atomicAdd(&g_U[(r0 + 8) * NBUK + n0 + 1], c.w);
        }
    }
}

// ---------------- finalize: out[c][b][k] = U[b][c*8+k] / Z_b ----------------
__global__ void finalize_kernel(float* __restrict__ out) {
    int b = blockIdx.x * blockDim.x + threadIdx.x;
    if (b >= B_ROWS) return;
    const float4* Urow = reinterpret_cast<const float4*>(&g_U[b * NBUK]);
    float4 u0 = Urow[0], u1 = Urow[1];
    float Z = u0.x + u0.y + u0.z + u0.w + u1.x + u1.y + u1.z + u1.w;
    float inv = 1.0f / Z;
    #pragma unroll
    for (int c = 0; c < 6; c++) {
        float4 a = Urow[c * 2], d = Urow[c * 2 + 1];
        a.x *= inv; a.y *= inv; a.z *= inv; a.w *= inv;
        d.x *= inv; d.y *= inv; d.z *= inv; d.w *= inv;
        float4* o = reinterpret_cast<float4*>(&out[c * (B_ROWS * 8) + b * 8]);
        o[0] = a;
        o[1] = d;
    }
}

// ---------------- launch ----------------
extern "C" void kernel_launch(void* const* d_in, const int* in_sizes, int n_in,
                              void* d_out, int out_size) {
    const float* E    = (const float*)d_in[0];   // [4096,1024]
    const float* W    = (const float*)d_in[1];   // [8192,1024]
    const float* bias = (const float*)d_in[2];   // [8192]
    const int*   vs   = (const int*)d_in[3];     // [8192]
    float* out = (float*)d_out;                  // [6,4096,8]

    conv_e_kernel<<<(B_ROWS * D_DIM / 4 + 255) / 256, 256>>>(E);
    conv_w_kernel<<<(NV * D_DIM / 4 + 255) / 256, 256>>>(W);
    build_s_kernel<<<(NBUK * NV + 255) / 256, 256>>>(vs);
    zero_u_kernel<<<(B_ROWS * NBUK / 4 + 255) / 256, 256>>>();

    gemm_exp_kernel<<<dim3(64, 32), 256>>>(bias);     // 2048 CTAs
    gemm_bucket_kernel<<<dim3(8, 32), 256>>>();       // 256 CTAs (split-K)
    finalize_kernel<<<(B_ROWS + 255) / 256, 256>>>(out);
}